// round 2
// baseline (speedup 1.0000x reference)
#include <cuda_runtime.h>

#define NB 8
#define NN 512
#define DD 256
#define DH 64
#define NROWS (NB*NN)   // 4096

// Scratch for projected Q, K, V (masked). 3 x 1 MB.
__device__ float g_Q[NROWS*DH];
__device__ float g_K[NROWS*DH];
__device__ float g_V[NROWS*DH];

// ---------------------------------------------------------------------------
// QKV projection: X(4096x256) @ {Wq,Wk,Wv}(256x64) + bias, then mask rows.
// 128 blocks x 256 threads; each block does 32 rows. W streamed from L2
// (192 KB total, reused 32x per block -> 24 MB L2 traffic).
// ---------------------------------------------------------------------------
__global__ __launch_bounds__(256) void qkv_kernel(
    const float* __restrict__ x, const int* __restrict__ mask,
    const float* __restrict__ Wq, const float* __restrict__ bq,
    const float* __restrict__ Wk, const float* __restrict__ bk,
    const float* __restrict__ Wv, const float* __restrict__ bv)
{
    __shared__ float xs[32*DD];                 // 32 KB
    const int row0 = blockIdx.x * 32;
    const int t = threadIdx.x;

    const float4* x4 = reinterpret_cast<const float4*>(x + (size_t)row0 * DD);
    float4* xs4 = reinterpret_cast<float4*>(xs);
    #pragma unroll
    for (int i = t; i < 32*DD/4; i += 256) xs4[i] = x4[i];
    __syncthreads();

    const int tx = t & 63;      // output column
    const int ty = t >> 6;      // 0..3 (row group)

    float accq[8], acck[8], accv[8];
    #pragma unroll
    for (int r = 0; r < 8; r++) { accq[r] = 0.f; acck[r] = 0.f; accv[r] = 0.f; }

    for (int k = 0; k < DD; k += 4) {
        float4 xv4[8];
        #pragma unroll
        for (int r = 0; r < 8; r++)
            xv4[r] = *reinterpret_cast<const float4*>(&xs[(ty + r*4)*DD + k]);
        #pragma unroll
        for (int kk = 0; kk < 4; kk++) {
            float wq = Wq[(k+kk)*DH + tx];
            float wk = Wk[(k+kk)*DH + tx];
            float wv = Wv[(k+kk)*DH + tx];
            #pragma unroll
            for (int r = 0; r < 8; r++) {
                float xv = reinterpret_cast<const float*>(&xv4[r])[kk];
                accq[r] = fmaf(xv, wq, accq[r]);
                acck[r] = fmaf(xv, wk, acck[r]);
                accv[r] = fmaf(xv, wv, accv[r]);
            }
        }
    }

    const float bqv = bq[tx], bkv = bk[tx], bvv = bv[tx];
    #pragma unroll
    for (int r = 0; r < 8; r++) {
        int row = row0 + ty + r*4;
        float m = (float)mask[row];
        g_Q[row*DH + tx] = (accq[r] + bqv) * m;
        g_K[row*DH + tx] = (acck[r] + bkv) * m;
        g_V[row*DH + tx] = (accv[r] + bvv) * m;
    }
}

// ---------------------------------------------------------------------------
// Attention: per block = 32 q-rows of one batch. 128 blocks x 256 threads.
// smem: Qs[32*64] + Ks[128*65] (pad->bank-conflict-free) + S[32*512] + Mj[512]
//     = 27264 floats = 106.5 KB dynamic.
// ---------------------------------------------------------------------------
#define SMEM_FLOATS 27264

__global__ __launch_bounds__(256) void attn_kernel(
    const int* __restrict__ mask, float* __restrict__ out)
{
    extern __shared__ float sm[];
    float* Qs = sm;                 // 2048
    float* Ks = sm + 2048;          // 8320 (128 rows, stride 65)
    float* S  = sm + 10368;         // 16384
    float* Mj = sm + 26752;         // 512

    const int b  = blockIdx.x >> 4;
    const int i0 = (blockIdx.x & 15) * 32;
    const int t  = threadIdx.x;

    for (int j = t; j < NN; j += 256) Mj[j] = (float)mask[b*NN + j];
    {
        const float4* q4 = reinterpret_cast<const float4*>(g_Q + (size_t)(b*NN + i0)*DH);
        float4* qs4 = reinterpret_cast<float4*>(Qs);
        for (int i = t; i < 32*DH/4; i += 256) qs4[i] = q4[i];
    }
    __syncthreads();

    const int tx = t & 31;          // j lane
    const int ty = t >> 5;          // 0..7 (i lane)

    // ---- scores: S[i][j] = mask ? (Q_i . K_j)/8 : -1e9 ----
    for (int jt = 0; jt < 4; jt++) {
        const int j0 = jt * 128;
        for (int idx = t; idx < 128*DH; idx += 256) {
            int j = idx >> 6, k = idx & 63;
            Ks[j*65 + k] = g_K[(size_t)(b*NN + j0 + j)*DH + k];
        }
        __syncthreads();

        float acc[4][4];
        #pragma unroll
        for (int c = 0; c < 4; c++)
            #pragma unroll
            for (int a = 0; a < 4; a++) acc[c][a] = 0.f;

        for (int k = 0; k < DH; k += 4) {
            float4 q4[4];
            #pragma unroll
            for (int c = 0; c < 4; c++)
                q4[c] = *reinterpret_cast<const float4*>(&Qs[(ty + 8*c)*DH + k]);
            #pragma unroll
            for (int kk = 0; kk < 4; kk++) {
                float kv[4];
                #pragma unroll
                for (int a = 0; a < 4; a++) kv[a] = Ks[(tx + 32*a)*65 + k + kk];
                #pragma unroll
                for (int c = 0; c < 4; c++) {
                    float qv = reinterpret_cast<const float*>(&q4[c])[kk];
                    #pragma unroll
                    for (int a = 0; a < 4; a++)
                        acc[c][a] = fmaf(qv, kv[a], acc[c][a]);
                }
            }
        }

        #pragma unroll
        for (int c = 0; c < 4; c++) {
            int i = ty + 8*c;
            float mi = Mj[i0 + i];
            #pragma unroll
            for (int a = 0; a < 4; a++) {
                int j = j0 + tx + 32*a;
                S[i*NN + j] = (mi * Mj[j] != 0.f) ? acc[c][a]*0.125f : -1.0e9f;
            }
        }
        __syncthreads();
    }

    // ---- softmax per row (warp-per-row, 4 rows per warp) ----
    {
        const int warp = t >> 5, lane = t & 31;
        for (int rr = 0; rr < 4; rr++) {
            int row = warp*4 + rr;
            float vals[16];
            float mx = -3.4e38f;
            #pragma unroll
            for (int m = 0; m < 16; m++) {
                vals[m] = S[row*NN + lane + 32*m];
                mx = fmaxf(mx, vals[m]);
            }
            #pragma unroll
            for (int o = 16; o > 0; o >>= 1)
                mx = fmaxf(mx, __shfl_xor_sync(0xffffffffu, mx, o));
            float sum = 0.f;
            #pragma unroll
            for (int m = 0; m < 16; m++) { vals[m] = __expf(vals[m] - mx); sum += vals[m]; }
            #pragma unroll
            for (int o = 16; o > 0; o >>= 1)
                sum += __shfl_xor_sync(0xffffffffu, sum, o);
            float inv = 1.f / sum;
            #pragma unroll
            for (int m = 0; m < 16; m++) S[row*NN + lane + 32*m] = vals[m]*inv;
        }
    }
    __syncthreads();

    // ---- out = P @ V, masked ----
    {
        const int tx4 = t & 15;       // dd group (4 cols)
        const int ty4 = t >> 4;       // rows ty4, ty4+16
        const int dd0 = tx4 * 4;
        const int i_a = ty4, i_b = ty4 + 16;
        float4 acc0 = {0,0,0,0}, acc1 = {0,0,0,0};
        const float4* V4 = reinterpret_cast<const float4*>(g_V + (size_t)b*NN*DH);
        #pragma unroll 4
        for (int j = 0; j < NN; j++) {
            float4 v = V4[j*(DH/4) + tx4];
            float sa = S[i_a*NN + j];
            float sb = S[i_b*NN + j];
            acc0.x = fmaf(sa, v.x, acc0.x); acc0.y = fmaf(sa, v.y, acc0.y);
            acc0.z = fmaf(sa, v.z, acc0.z); acc0.w = fmaf(sa, v.w, acc0.w);
            acc1.x = fmaf(sb, v.x, acc1.x); acc1.y = fmaf(sb, v.y, acc1.y);
            acc1.z = fmaf(sb, v.z, acc1.z); acc1.w = fmaf(sb, v.w, acc1.w);
        }
        float ma = Mj[i0 + i_a], mb = Mj[i0 + i_b];
        acc0.x *= ma; acc0.y *= ma; acc0.z *= ma; acc0.w *= ma;
        acc1.x *= mb; acc1.y *= mb; acc1.z *= mb; acc1.w *= mb;
        float4* o4 = reinterpret_cast<float4*>(out);
        o4[((size_t)(b*NN + i0 + i_a)*DH + dd0) >> 2] = acc0;
        o4[((size_t)(b*NN + i0 + i_b)*DH + dd0) >> 2] = acc1;
    }
}

// ---------------------------------------------------------------------------
extern "C" void kernel_launch(void* const* d_in, const int* in_sizes, int n_in,
                              void* d_out, int out_size)
{
    const float* x  = (const float*)d_in[0];
    const float* e  = (const float*)d_in[1];
    const int*  msk = (const int*)  d_in[2];
    const float* Wq = (const float*)d_in[3];
    const float* bq = (const float*)d_in[4];
    const float* Wk = (const float*)d_in[5];
    const float* bk = (const float*)d_in[6];
    const float* Wv = (const float*)d_in[7];
    const float* bv = (const float*)d_in[8];
    float* out = (float*)d_out;

    qkv_kernel<<<128, 256>>>(x, msk, Wq, bq, Wk, bk, Wv, bv);

    cudaFuncSetAttribute(attn_kernel, cudaFuncAttributeMaxDynamicSharedMemorySize,
                         SMEM_FLOATS * (int)sizeof(float));
    attn_kernel<<<128, 256, SMEM_FLOATS * sizeof(float)>>>(msk, out);

    // e passthrough: (8,512,512,32) f32 = 256 MB, appended after out.
    cudaMemcpyAsync(out + (size_t)NROWS*DH, e,
                    (size_t)NB*NN*NN*32*sizeof(float),
                    cudaMemcpyDeviceToDevice, 0);
}